// round 3
// baseline (speedup 1.0000x reference)
#include <cuda_runtime.h>
#include <math.h>

#define NN 1200000
#define EE 12000000
#define BB 200000

// ---------------- scratch (device globals: allocation-free) ----------------
__device__ __align__(16) float g_deg[NN];
__device__ __align__(16) float g_dinv[NN];
__device__ __align__(16) float g_hs1[(size_t)NN * 20];   // h1 * dinv   (96MB)
__device__ __align__(16) float g_agg1[(size_t)NN * 20];  // layer1 agg  (96MB)
__device__ __align__(16) float g_hs2[(size_t)NN * 8];    // h2 * dinv, padded to 8
__device__ __align__(16) float g_agg2[(size_t)NN * 8];   // layer2 agg, padded to 8

// sin(0..9): positional encoding (d_model=1 -> only sin slice)
__constant__ float PO[10] = {
    0.0f, 0.8414709848f, 0.9092974268f, 0.1411200081f, -0.7568024953f,
    -0.9589242747f, -0.2794154982f, 0.6569865987f, 0.9893582466f, 0.4121184852f
};

__device__ __forceinline__ float gelu_f(float x) {
    // exact gelu: 0.5 x (1 + erf(x / sqrt(2)))
    return 0.5f * x * (1.0f + erff(x * 0.7071067811865475f));
}

// sm_90+ vector reduction: 4 float adds in one red op, 16B-aligned address
__device__ __forceinline__ void red4(float* p, float a, float b, float c, float d) {
    asm volatile("red.global.add.v4.f32 [%0], {%1,%2,%3,%4};"
                 :: "l"(p), "f"(a), "f"(b), "f"(c), "f"(d) : "memory");
}

// ---------------- kernels ----------------

__global__ void k_init_deg() {
    int n = blockIdx.x * blockDim.x + threadIdx.x;
    if (n < NN) g_deg[n] = 1.0f;   // self-loop in degree
}

__global__ void k_deg(const int* __restrict__ ei) {
    int e = blockIdx.x * blockDim.x + threadIdx.x;
    if (e < EE) atomicAdd(&g_deg[ei[EE + e]], 1.0f);
}

// node pass 1: dinv, h1 = (x+po)@W1, hs1 = h1*dinv, agg1 = hs1*dinv (self term)
__global__ void k_layer1(const float* __restrict__ x, const float* __restrict__ W1) {
    __shared__ float sW[200];
    for (int i = threadIdx.x; i < 200; i += blockDim.x) sW[i] = W1[i];
    __syncthreads();
    int n = blockIdx.x * blockDim.x + threadIdx.x;
    if (n >= NN) return;

    float xr[10];
    const float2* xp = (const float2*)(x + (size_t)n * 10);  // 8B aligned always
    #pragma unroll
    for (int i = 0; i < 5; i++) {
        float2 v = xp[i];
        xr[2 * i]     = v.x + PO[2 * i];
        xr[2 * i + 1] = v.y + PO[2 * i + 1];
    }
    float h[20];
    #pragma unroll
    for (int j = 0; j < 20; j++) h[j] = 0.0f;
    #pragma unroll
    for (int i = 0; i < 10; i++) {
        float xi = xr[i];
        #pragma unroll
        for (int j = 0; j < 20; j++) h[j] = fmaf(xi, sW[i * 20 + j], h[j]);
    }
    float di = rsqrtf(g_deg[n]);
    g_dinv[n] = di;
    float4* hp = (float4*)(g_hs1 + (size_t)n * 20);
    float4* ap = (float4*)(g_agg1 + (size_t)n * 20);
    #pragma unroll
    for (int q = 0; q < 5; q++) {
        float4 v;
        v.x = h[4 * q + 0] * di; v.y = h[4 * q + 1] * di;
        v.z = h[4 * q + 2] * di; v.w = h[4 * q + 3] * di;
        hp[q] = v;
        float4 a;
        a.x = v.x * di; a.y = v.y * di; a.z = v.z * di; a.w = v.w * di;
        ap[q] = a;
    }
}

// edge scatter layer 1: agg1[dst] += hs1[src] * dinv[dst]   (5 x red.v4)
__global__ void k_scatter1(const int* __restrict__ ei) {
    int e = blockIdx.x * blockDim.x + threadIdx.x;
    if (e >= EE) return;
    int s = ei[e];
    int d = ei[EE + e];
    float w = g_dinv[d];
    const float4* hp = (const float4*)(g_hs1 + (size_t)s * 20);
    float* ap = g_agg1 + (size_t)d * 20;
    #pragma unroll
    for (int q = 0; q < 5; q++) {
        float4 v = hp[q];
        red4(ap + 4 * q, v.x * w, v.y * w, v.z * w, v.w * w);
    }
}

// node pass 2: x2 = gelu(agg1+b1), h2 = x2@W2, hs2 = h2*dinv, agg2 = hs2*dinv
__global__ void k_layer2(const float* __restrict__ W2, const float* __restrict__ b1) {
    __shared__ float sW[100];
    __shared__ float sb[20];
    for (int i = threadIdx.x; i < 100; i += blockDim.x) sW[i] = W2[i];
    for (int i = threadIdx.x; i < 20; i += blockDim.x) sb[i] = b1[i];
    __syncthreads();
    int n = blockIdx.x * blockDim.x + threadIdx.x;
    if (n >= NN) return;

    const float4* ap = (const float4*)(g_agg1 + (size_t)n * 20);
    float x2[20];
    #pragma unroll
    for (int q = 0; q < 5; q++) {
        float4 v = ap[q];
        x2[4 * q + 0] = gelu_f(v.x + sb[4 * q + 0]);
        x2[4 * q + 1] = gelu_f(v.y + sb[4 * q + 1]);
        x2[4 * q + 2] = gelu_f(v.z + sb[4 * q + 2]);
        x2[4 * q + 3] = gelu_f(v.w + sb[4 * q + 3]);
    }
    float h[5] = {0.f, 0.f, 0.f, 0.f, 0.f};
    #pragma unroll
    for (int i = 0; i < 20; i++) {
        float xi = x2[i];
        #pragma unroll
        for (int j = 0; j < 5; j++) h[j] = fmaf(xi, sW[i * 5 + j], h[j]);
    }
    float di = g_dinv[n];
    float4* hp  = (float4*)(g_hs2  + (size_t)n * 8);
    float4* agp = (float4*)(g_agg2 + (size_t)n * 8);
    float4 v0 = make_float4(h[0] * di, h[1] * di, h[2] * di, h[3] * di);
    float4 v1 = make_float4(h[4] * di, 0.f, 0.f, 0.f);
    hp[0] = v0; hp[1] = v1;
    float4 a0 = make_float4(v0.x * di, v0.y * di, v0.z * di, v0.w * di);
    float4 a1 = make_float4(v1.x * di, 0.f, 0.f, 0.f);
    agp[0] = a0; agp[1] = a1;
}

// edge scatter layer 2: agg2[dst] += hs2[src] * dinv[dst]  (red.v4 + scalar)
__global__ void k_scatter2(const int* __restrict__ ei) {
    int e = blockIdx.x * blockDim.x + threadIdx.x;
    if (e >= EE) return;
    int s = ei[e];
    int d = ei[EE + e];
    float w = g_dinv[d];
    const float4* hp = (const float4*)(g_hs2 + (size_t)s * 8);
    float4 v0 = hp[0];
    float4 v1 = hp[1];
    float* ap = g_agg2 + (size_t)d * 8;
    red4(ap, v0.x * w, v0.y * w, v0.z * w, v0.w * w);
    atomicAdd(ap + 4, v1.x * w);
}

// dense heads: r = gelu(agg2+b2) reshaped [B,30]; enc=r@We+be;
// x1=enc@Wr+br; out=gelu(enc)@Wd+bd.  d_out = [x1 | enc | out] flattened.
__global__ void k_head(const float* __restrict__ b2,
                       const float* __restrict__ We, const float* __restrict__ be,
                       const float* __restrict__ Wd, const float* __restrict__ bd,
                       const float* __restrict__ Wr, const float* __restrict__ br,
                       float* __restrict__ out) {
    __shared__ float sWe[900], sWd[1800], sWr[210];
    __shared__ float sbe[30], sbd[60], sbr[7], sb2[5];
    for (int i = threadIdx.x; i < 900; i += blockDim.x) sWe[i] = We[i];
    for (int i = threadIdx.x; i < 1800; i += blockDim.x) sWd[i] = Wd[i];
    for (int i = threadIdx.x; i < 210; i += blockDim.x) sWr[i] = Wr[i];
    if (threadIdx.x < 30) sbe[threadIdx.x] = be[threadIdx.x];
    if (threadIdx.x < 60) sbd[threadIdx.x] = bd[threadIdx.x];
    if (threadIdx.x < 7)  sbr[threadIdx.x] = br[threadIdx.x];
    if (threadIdx.x < 5)  sb2[threadIdx.x] = b2[threadIdx.x];
    __syncthreads();
    int b = blockIdx.x * blockDim.x + threadIdx.x;
    if (b >= BB) return;

    float r[30];
    #pragma unroll
    for (int v = 0; v < 6; v++) {
        const float* ag = g_agg2 + (size_t)(b * 6 + v) * 8;
        #pragma unroll
        for (int c = 0; c < 5; c++) r[v * 5 + c] = gelu_f(ag[c] + sb2[c]);
    }
    float enc[30];
    #pragma unroll 1
    for (int j = 0; j < 30; j++) {
        float a = sbe[j];
        #pragma unroll
        for (int k = 0; k < 30; k++) a = fmaf(r[k], sWe[k * 30 + j], a);
        enc[j] = a;
    }
    float* x1o  = out;
    float* enco = out + (size_t)BB * 7;
    float* oo   = out + (size_t)BB * 37;
    #pragma unroll 1
    for (int j = 0; j < 7; j++) {
        float a = sbr[j];
        #pragma unroll
        for (int k = 0; k < 30; k++) a = fmaf(enc[k], sWr[k * 7 + j], a);
        x1o[(size_t)b * 7 + j] = a;
    }
    float ge[30];
    #pragma unroll
    for (int k = 0; k < 30; k++) {
        enco[(size_t)b * 30 + k] = enc[k];
        ge[k] = gelu_f(enc[k]);
    }
    #pragma unroll 1
    for (int j = 0; j < 60; j++) {
        float a = sbd[j];
        #pragma unroll
        for (int k = 0; k < 30; k++) a = fmaf(ge[k], sWd[k * 60 + j], a);
        oo[(size_t)b * 60 + j] = a;
    }
}

// ---------------- launch ----------------
extern "C" void kernel_launch(void* const* d_in, const int* in_sizes, int n_in,
                              void* d_out, int out_size) {
    const float* x  = (const float*)d_in[0];
    const int*   ei = (const int*)  d_in[1];
    const float* W1 = (const float*)d_in[2];
    const float* b1 = (const float*)d_in[3];
    const float* W2 = (const float*)d_in[4];
    const float* b2 = (const float*)d_in[5];
    const float* We = (const float*)d_in[6];
    const float* be = (const float*)d_in[7];
    const float* Wd = (const float*)d_in[8];
    const float* bd = (const float*)d_in[9];
    const float* Wr = (const float*)d_in[10];
    const float* br = (const float*)d_in[11];
    float* out = (float*)d_out;

    const int TB = 256;
    k_init_deg<<<(NN + TB - 1) / TB, TB>>>();
    k_deg<<<(EE + TB - 1) / TB, TB>>>(ei);
    k_layer1<<<(NN + TB - 1) / TB, TB>>>(x, W1);
    k_scatter1<<<(EE + TB - 1) / TB, TB>>>(ei);
    k_layer2<<<(NN + TB - 1) / TB, TB>>>(W2, b1);
    k_scatter2<<<(EE + TB - 1) / TB, TB>>>(ei);
    k_head<<<(BB + 127) / 128, 128>>>(b2, We, be, Wd, bd, Wr, br, out);
}

// round 5
// speedup vs baseline: 1.6706x; 1.6706x over previous
#include <cuda_runtime.h>
#include <math.h>

#define NN 1200000
#define EE 12000000
#define BB 200000

// ---------------- scratch (device globals: allocation-free) ----------------
__device__ __align__(16) float g_deg[NN];
__device__ __align__(16) float g_dinv[NN];
__device__ __align__(16) float g_xs1[(size_t)NN * 12];   // (x+po)*dinv, pad 12 (57.6MB)
__device__ __align__(16) float g_agg1[(size_t)NN * 12];  // raw layer1 sums (57.6MB)
__device__ __align__(16) float g_ys2[(size_t)NN * 8];    // h2*dinv, pad 8  (38.4MB)
__device__ __align__(16) float g_agg2[(size_t)NN * 8];   // raw layer2 sums (38.4MB)

// sin(0..9): positional encoding (d_model=1 -> only sin slice)
__constant__ float PO[10] = {
    0.0f, 0.8414709848f, 0.9092974268f, 0.1411200081f, -0.7568024953f,
    -0.9589242747f, -0.2794154982f, 0.6569865987f, 0.9893582466f, 0.4121184852f
};

__device__ __forceinline__ float gelu_f(float x) {
    return 0.5f * x * (1.0f + erff(x * 0.7071067811865475f));
}

__device__ __forceinline__ void red4(float* p, float a, float b, float c, float d) {
    asm volatile("red.global.add.v4.f32 [%0], {%1,%2,%3,%4};"
                 :: "l"(p), "f"(a), "f"(b), "f"(c), "f"(d) : "memory");
}
__device__ __forceinline__ void red2(float* p, float a, float b) {
    asm volatile("red.global.add.v2.f32 [%0], {%1,%2};"
                 :: "l"(p), "f"(a), "f"(b) : "memory");
}

// ---------------- kernels ----------------

__global__ void k_init_deg() {
    int n = blockIdx.x * blockDim.x + threadIdx.x;
    if (n < NN) g_deg[n] = 1.0f;   // self-loop
}

__global__ void k_deg(const int* __restrict__ ei) {
    int e = blockIdx.x * blockDim.x + threadIdx.x;
    if (e < EE) atomicAdd(&g_deg[ei[EE + e]], 1.0f);
}

// prep: dinv, xs1 = (x+po)*dinv (pad 12), agg1_raw = xs1 (self-loop term)
__global__ void k_prep(const float* __restrict__ x) {
    int n = blockIdx.x * blockDim.x + threadIdx.x;
    if (n >= NN) return;
    float di = rsqrtf(g_deg[n]);
    g_dinv[n] = di;

    const float2* xp = (const float2*)(x + (size_t)n * 10);
    float v[12];
    #pragma unroll
    for (int i = 0; i < 5; i++) {
        float2 t = xp[i];
        v[2 * i]     = (t.x + PO[2 * i]) * di;
        v[2 * i + 1] = (t.y + PO[2 * i + 1]) * di;
    }
    v[10] = 0.0f; v[11] = 0.0f;
    float4* sp = (float4*)(g_xs1 + (size_t)n * 12);
    float4* ap = (float4*)(g_agg1 + (size_t)n * 12);
    #pragma unroll
    for (int q = 0; q < 3; q++) {
        float4 w = make_float4(v[4*q], v[4*q+1], v[4*q+2], v[4*q+3]);
        sp[q] = w;
        ap[q] = w;
    }
}

// edge scatter layer 1: agg1_raw[dst] += xs1[src]   (10 useful floats)
__global__ void k_scatter1(const int* __restrict__ ei) {
    int e = blockIdx.x * blockDim.x + threadIdx.x;
    if (e >= EE) return;
    int s = ei[e];
    int d = ei[EE + e];
    const float4* sp = (const float4*)(g_xs1 + (size_t)s * 12);
    float4 v0 = sp[0];
    float4 v1 = sp[1];
    float2 v2 = *(const float2*)(sp + 2);
    float* ap = g_agg1 + (size_t)d * 12;
    red4(ap,     v0.x, v0.y, v0.z, v0.w);
    red4(ap + 4, v1.x, v1.y, v1.z, v1.w);
    red2(ap + 8, v2.x, v2.y);
}

// mid: u = dinv*agg1_raw; x2 = gelu(u@W1 + b1); h2 = x2@W2;
//      ys2 = h2*dinv (pad 8); agg2_raw = ys2 (self-loop term)
__global__ void k_mid(const float* __restrict__ W1, const float* __restrict__ b1,
                      const float* __restrict__ W2) {
    __shared__ float sW1[200], sW2[100], sb1[20];
    for (int i = threadIdx.x; i < 200; i += blockDim.x) sW1[i] = W1[i];
    for (int i = threadIdx.x; i < 100; i += blockDim.x) sW2[i] = W2[i];
    for (int i = threadIdx.x; i < 20;  i += blockDim.x) sb1[i] = b1[i];
    __syncthreads();
    int n = blockIdx.x * blockDim.x + threadIdx.x;
    if (n >= NN) return;

    float di = g_dinv[n];
    const float4* ap = (const float4*)(g_agg1 + (size_t)n * 12);
    float u[10];
    float4 a0 = ap[0], a1 = ap[1];
    float2 a2 = *(const float2*)(ap + 2);
    u[0]=a0.x*di; u[1]=a0.y*di; u[2]=a0.z*di; u[3]=a0.w*di;
    u[4]=a1.x*di; u[5]=a1.y*di; u[6]=a1.z*di; u[7]=a1.w*di;
    u[8]=a2.x*di; u[9]=a2.y*di;

    float h1[20];
    #pragma unroll
    for (int j = 0; j < 20; j++) h1[j] = sb1[j];
    #pragma unroll
    for (int i = 0; i < 10; i++) {
        float xi = u[i];
        #pragma unroll
        for (int j = 0; j < 20; j++) h1[j] = fmaf(xi, sW1[i * 20 + j], h1[j]);
    }
    float h2[5] = {0.f, 0.f, 0.f, 0.f, 0.f};
    #pragma unroll
    for (int i = 0; i < 20; i++) {
        float xi = gelu_f(h1[i]);
        #pragma unroll
        for (int j = 0; j < 5; j++) h2[j] = fmaf(xi, sW2[i * 5 + j], h2[j]);
    }
    float4* yp = (float4*)(g_ys2 + (size_t)n * 8);
    float4* gp = (float4*)(g_agg2 + (size_t)n * 8);
    float4 v0 = make_float4(h2[0]*di, h2[1]*di, h2[2]*di, h2[3]*di);
    float4 v1 = make_float4(h2[4]*di, 0.f, 0.f, 0.f);
    yp[0] = v0; yp[1] = v1;
    gp[0] = v0; gp[1] = v1;
}

// edge scatter layer 2: agg2_raw[dst] += ys2[src]  (5 useful floats)
__global__ void k_scatter2(const int* __restrict__ ei) {
    int e = blockIdx.x * blockDim.x + threadIdx.x;
    if (e >= EE) return;
    int s = ei[e];
    int d = ei[EE + e];
    const float4* sp = (const float4*)(g_ys2 + (size_t)s * 8);
    float4 v0 = sp[0];
    float  v4 = *((const float*)(sp + 1));
    float* ap = g_agg2 + (size_t)d * 8;
    red4(ap, v0.x, v0.y, v0.z, v0.w);
    atomicAdd(ap + 4, v4);
}

// heads: r = gelu(dinv*agg2_raw + b2) reshaped [B,30]; enc=r@We+be;
// x1=enc@Wr+br; out=gelu(enc)@Wd+bd.  d_out = [x1 | enc | out]
__global__ void k_head(const float* __restrict__ b2,
                       const float* __restrict__ We, const float* __restrict__ be,
                       const float* __restrict__ Wd, const float* __restrict__ bd,
                       const float* __restrict__ Wr, const float* __restrict__ br,
                       float* __restrict__ out) {
    __shared__ float sWe[900], sWd[1800], sWr[210];
    __shared__ float sbe[30], sbd[60], sbr[7], sb2[5];
    for (int i = threadIdx.x; i < 900; i += blockDim.x) sWe[i] = We[i];
    for (int i = threadIdx.x; i < 1800; i += blockDim.x) sWd[i] = Wd[i];
    for (int i = threadIdx.x; i < 210; i += blockDim.x) sWr[i] = Wr[i];
    if (threadIdx.x < 30) sbe[threadIdx.x] = be[threadIdx.x];
    if (threadIdx.x < 60) sbd[threadIdx.x] = bd[threadIdx.x];
    if (threadIdx.x < 7)  sbr[threadIdx.x] = br[threadIdx.x];
    if (threadIdx.x < 5)  sb2[threadIdx.x] = b2[threadIdx.x];
    __syncthreads();
    int b = blockIdx.x * blockDim.x + threadIdx.x;
    if (b >= BB) return;

    float r[30];
    #pragma unroll
    for (int v = 0; v < 6; v++) {
        int n = b * 6 + v;
        float di = g_dinv[n];
        const float* ag = g_agg2 + (size_t)n * 8;
        #pragma unroll
        for (int c = 0; c < 5; c++) r[v * 5 + c] = gelu_f(ag[c] * di + sb2[c]);
    }
    float enc[30];
    #pragma unroll 1
    for (int j = 0; j < 30; j++) {
        float a = sbe[j];
        #pragma unroll
        for (int k = 0; k < 30; k++) a = fmaf(r[k], sWe[k * 30 + j], a);
        enc[j] = a;
    }
    float* x1o  = out;
    float* enco = out + (size_t)BB * 7;
    float* oo   = out + (size_t)BB * 37;
    #pragma unroll 1
    for (int j = 0; j < 7; j++) {
        float a = sbr[j];
        #pragma unroll
        for (int k = 0; k < 30; k++) a = fmaf(enc[k], sWr[k * 7 + j], a);
        x1o[(size_t)b * 7 + j] = a;
    }
    float ge[30];
    #pragma unroll
    for (int k = 0; k < 30; k++) {
        enco[(size_t)b * 30 + k] = enc[k];
        ge[k] = gelu_f(enc[k]);
    }
    #pragma unroll 1
    for (int j = 0; j < 60; j++) {
        float a = sbd[j];
        #pragma unroll
        for (int k = 0; k < 30; k++) a = fmaf(ge[k], sWd[k * 60 + j], a);
        oo[(size_t)b * 60 + j] = a;
    }
}

// ---------------- launch ----------------
extern "C" void kernel_launch(void* const* d_in, const int* in_sizes, int n_in,
                              void* d_out, int out_size) {
    const float* x  = (const float*)d_in[0];
    const int*   ei = (const int*)  d_in[1];
    const float* W1 = (const float*)d_in[2];
    const float* b1 = (const float*)d_in[3];
    const float* W2 = (const float*)d_in[4];
    const float* b2 = (const float*)d_in[5];
    const float* We = (const float*)d_in[6];
    const float* be = (const float*)d_in[7];
    const float* Wd = (const float*)d_in[8];
    const float* bd = (const float*)d_in[9];
    const float* Wr = (const float*)d_in[10];
    const float* br = (const float*)d_in[11];
    float* out = (float*)d_out;

    const int TB = 256;
    k_init_deg<<<(NN + TB - 1) / TB, TB>>>();
    k_deg<<<(EE + TB - 1) / TB, TB>>>(ei);
    k_prep<<<(NN + TB - 1) / TB, TB>>>(x);
    k_scatter1<<<(EE + TB - 1) / TB, TB>>>(ei);
    k_mid<<<(NN + TB - 1) / TB, TB>>>(W1, b1, W2);
    k_scatter2<<<(EE + TB - 1) / TB, TB>>>(ei);
    k_head<<<(BB + 127) / 128, 128>>>(b2, We, be, Wd, bd, Wr, br, out);
}

// round 12
// speedup vs baseline: 1.7934x; 1.0735x over previous
#include <cuda_runtime.h>
#include <math.h>

#define NN 1200000
#define EE 12000000
#define BB 200000

// ---------------- scratch (device globals: allocation-free) ----------------
__device__ __align__(16) float g_deg[NN];
__device__ __align__(16) float g_dinv[NN];
// layer-1 features split: 8-float rows (32B sector-aligned) + 2-float rows
__device__ __align__(32) float g_xs1a[(size_t)NN * 8];   // comps 0-7  (38.4MB)
__device__ __align__(16) float g_xs1b[(size_t)NN * 2];   // comps 8-9  ( 9.6MB)
__device__ __align__(32) float g_agg1a[(size_t)NN * 8];  // raw sums   (38.4MB)
__device__ __align__(16) float g_agg1b[(size_t)NN * 2];  //            ( 9.6MB)
// layer-2: 8-float padded rows (one 32B sector per row)
__device__ __align__(32) float g_ys2[(size_t)NN * 8];    // h2*dinv    (38.4MB)
__device__ __align__(32) float g_agg2[(size_t)NN * 8];   // raw sums   (38.4MB)

// sin(0..9): positional encoding (d_model=1 -> only sin slice)
__constant__ float PO[10] = {
    0.0f, 0.8414709848f, 0.9092974268f, 0.1411200081f, -0.7568024953f,
    -0.9589242747f, -0.2794154982f, 0.6569865987f, 0.9893582466f, 0.4121184852f
};

__device__ __forceinline__ float gelu_f(float x) {
    return 0.5f * x * (1.0f + erff(x * 0.7071067811865475f));
}

__device__ __forceinline__ void red4(float* p, float a, float b, float c, float d) {
    asm volatile("red.global.add.v4.f32 [%0], {%1,%2,%3,%4};"
                 :: "l"(p), "f"(a), "f"(b), "f"(c), "f"(d) : "memory");
}
__device__ __forceinline__ void red2(float* p, float a, float b) {
    asm volatile("red.global.add.v2.f32 [%0], {%1,%2};"
                 :: "l"(p), "f"(a), "f"(b) : "memory");
}
// streaming 256-bit load of 8 edge indices: evict_first so the 96MB index
// stream doesn't evict the L2-resident feature/accumulator arrays.
// (sm_103 ptxas only accepts .L2::evict_first on .v8.b32 / .v4.b64 loads.)
__device__ __forceinline__ void ldg_stream8(const int* p, int* v) {
    asm volatile("ld.global.nc.L2::evict_first.v8.b32 "
                 "{%0,%1,%2,%3,%4,%5,%6,%7}, [%8];"
                 : "=r"(v[0]), "=r"(v[1]), "=r"(v[2]), "=r"(v[3]),
                   "=r"(v[4]), "=r"(v[5]), "=r"(v[6]), "=r"(v[7])
                 : "l"(p));
}

// ---------------- kernels ----------------

__global__ void k_init_deg() {
    int n = blockIdx.x * blockDim.x + threadIdx.x;
    if (n < NN) g_deg[n] = 1.0f;   // self-loop
}

// 8 edges per thread
__global__ void k_deg(const int* __restrict__ ei) {
    int t = blockIdx.x * blockDim.x + threadIdx.x;
    int e0 = t * 8;
    if (e0 >= EE) return;
    int d[8];
    ldg_stream8(ei + EE + e0, d);
    #pragma unroll
    for (int i = 0; i < 8; i++) atomicAdd(&g_deg[d[i]], 1.0f);
}

// prep: dinv, xs1 = (x+po)*dinv  (split 8+2), agg1_raw = xs1 (self-loop term)
__global__ void k_prep(const float* __restrict__ x) {
    int n = blockIdx.x * blockDim.x + threadIdx.x;
    if (n >= NN) return;
    float di = rsqrtf(g_deg[n]);
    g_dinv[n] = di;

    const float2* xp = (const float2*)(x + (size_t)n * 10);
    float v[10];
    #pragma unroll
    for (int i = 0; i < 5; i++) {
        float2 t = xp[i];
        v[2 * i]     = (t.x + PO[2 * i]) * di;
        v[2 * i + 1] = (t.y + PO[2 * i + 1]) * di;
    }
    float4 w0 = make_float4(v[0], v[1], v[2], v[3]);
    float4 w1 = make_float4(v[4], v[5], v[6], v[7]);
    float2 w2 = make_float2(v[8], v[9]);
    float4* sa = (float4*)(g_xs1a + (size_t)n * 8);
    float4* aa = (float4*)(g_agg1a + (size_t)n * 8);
    sa[0] = w0; sa[1] = w1;
    aa[0] = w0; aa[1] = w1;
    *(float2*)(g_xs1b  + (size_t)n * 2) = w2;
    *(float2*)(g_agg1b + (size_t)n * 2) = w2;
}

// edge scatter layer 1: agg1_raw[dst] += xs1[src], 8 edges/thread
__global__ void k_scatter1(const int* __restrict__ ei) {
    int t = blockIdx.x * blockDim.x + threadIdx.x;
    int e0 = t * 8;
    if (e0 >= EE) return;
    int s[8], d[8];
    ldg_stream8(ei + e0, s);
    ldg_stream8(ei + EE + e0, d);
    // issue all gathers first (MLP), then the reductions
    float4 v0[8], v1[8];
    float2 v2[8];
    #pragma unroll
    for (int i = 0; i < 8; i++) {
        const float4* sa = (const float4*)(g_xs1a + (size_t)s[i] * 8);
        v0[i] = __ldg(sa);
        v1[i] = __ldg(sa + 1);
        v2[i] = __ldg((const float2*)(g_xs1b + (size_t)s[i] * 2));
    }
    #pragma unroll
    for (int i = 0; i < 8; i++) {
        float* aa = g_agg1a + (size_t)d[i] * 8;
        red4(aa,     v0[i].x, v0[i].y, v0[i].z, v0[i].w);
        red4(aa + 4, v1[i].x, v1[i].y, v1[i].z, v1[i].w);
        red2(g_agg1b + (size_t)d[i] * 2, v2[i].x, v2[i].y);
    }
}

// mid: u = dinv*agg1_raw; x2 = gelu(u@W1 + b1); h2 = x2@W2;
//      ys2 = h2*dinv (pad 8); agg2_raw = ys2 (self-loop term)
__global__ void k_mid(const float* __restrict__ W1, const float* __restrict__ b1,
                      const float* __restrict__ W2) {
    __shared__ float sW1[200], sW2[100], sb1[20];
    for (int i = threadIdx.x; i < 200; i += blockDim.x) sW1[i] = W1[i];
    for (int i = threadIdx.x; i < 100; i += blockDim.x) sW2[i] = W2[i];
    for (int i = threadIdx.x; i < 20;  i += blockDim.x) sb1[i] = b1[i];
    __syncthreads();
    int n = blockIdx.x * blockDim.x + threadIdx.x;
    if (n >= NN) return;

    float di = g_dinv[n];
    const float4* aa = (const float4*)(g_agg1a + (size_t)n * 8);
    float4 a0 = aa[0], a1 = aa[1];
    float2 a2 = *(const float2*)(g_agg1b + (size_t)n * 2);
    float u[10];
    u[0]=a0.x*di; u[1]=a0.y*di; u[2]=a0.z*di; u[3]=a0.w*di;
    u[4]=a1.x*di; u[5]=a1.y*di; u[6]=a1.z*di; u[7]=a1.w*di;
    u[8]=a2.x*di; u[9]=a2.y*di;

    float h1[20];
    #pragma unroll
    for (int j = 0; j < 20; j++) h1[j] = sb1[j];
    #pragma unroll
    for (int i = 0; i < 10; i++) {
        float xi = u[i];
        #pragma unroll
        for (int j = 0; j < 20; j++) h1[j] = fmaf(xi, sW1[i * 20 + j], h1[j]);
    }
    float h2[5] = {0.f, 0.f, 0.f, 0.f, 0.f};
    #pragma unroll
    for (int i = 0; i < 20; i++) {
        float xi = gelu_f(h1[i]);
        #pragma unroll
        for (int j = 0; j < 5; j++) h2[j] = fmaf(xi, sW2[i * 5 + j], h2[j]);
    }
    float4* yp = (float4*)(g_ys2 + (size_t)n * 8);
    float4* gp = (float4*)(g_agg2 + (size_t)n * 8);
    float4 v0 = make_float4(h2[0]*di, h2[1]*di, h2[2]*di, h2[3]*di);
    float4 v1 = make_float4(h2[4]*di, 0.f, 0.f, 0.f);
    yp[0] = v0; yp[1] = v1;
    gp[0] = v0; gp[1] = v1;
}

// edge scatter layer 2: agg2_raw[dst] += ys2[src], 8 edges/thread
__global__ void k_scatter2(const int* __restrict__ ei) {
    int t = blockIdx.x * blockDim.x + threadIdx.x;
    int e0 = t * 8;
    if (e0 >= EE) return;
    int s[8], d[8];
    ldg_stream8(ei + e0, s);
    ldg_stream8(ei + EE + e0, d);
    float4 v0[8];
    float  v4[8];
    #pragma unroll
    for (int i = 0; i < 8; i++) {
        const float4* sp = (const float4*)(g_ys2 + (size_t)s[i] * 8);
        v0[i] = __ldg(sp);
        v4[i] = __ldg((const float*)(sp + 1));
    }
    #pragma unroll
    for (int i = 0; i < 8; i++) {
        float* ap = g_agg2 + (size_t)d[i] * 8;
        red4(ap, v0[i].x, v0[i].y, v0[i].z, v0[i].w);
        atomicAdd(ap + 4, v4[i]);
    }
}

// heads: r = gelu(dinv*agg2_raw + b2) reshaped [B,30]; enc=r@We+be;
// x1=enc@Wr+br; out=gelu(enc)@Wd+bd.  d_out = [x1 | enc | out]
__global__ void k_head(const float* __restrict__ b2,
                       const float* __restrict__ We, const float* __restrict__ be,
                       const float* __restrict__ Wd, const float* __restrict__ bd,
                       const float* __restrict__ Wr, const float* __restrict__ br,
                       float* __restrict__ out) {
    __shared__ float sWe[900], sWd[1800], sWr[210];
    __shared__ float sbe[30], sbd[60], sbr[7], sb2[5];
    for (int i = threadIdx.x; i < 900; i += blockDim.x) sWe[i] = We[i];
    for (int i = threadIdx.x; i < 1800; i += blockDim.x) sWd[i] = Wd[i];
    for (int i = threadIdx.x; i < 210; i += blockDim.x) sWr[i] = Wr[i];
    if (threadIdx.x < 30) sbe[threadIdx.x] = be[threadIdx.x];
    if (threadIdx.x < 60) sbd[threadIdx.x] = bd[threadIdx.x];
    if (threadIdx.x < 7)  sbr[threadIdx.x] = br[threadIdx.x];
    if (threadIdx.x < 5)  sb2[threadIdx.x] = b2[threadIdx.x];
    __syncthreads();
    int b = blockIdx.x * blockDim.x + threadIdx.x;
    if (b >= BB) return;

    float r[30];
    #pragma unroll
    for (int v = 0; v < 6; v++) {
        int n = b * 6 + v;
        float di = g_dinv[n];
        const float* ag = g_agg2 + (size_t)n * 8;
        #pragma unroll
        for (int c = 0; c < 5; c++) r[v * 5 + c] = gelu_f(ag[c] * di + sb2[c]);
    }
    float enc[30];
    #pragma unroll 1
    for (int j = 0; j < 30; j++) {
        float a = sbe[j];
        #pragma unroll
        for (int k = 0; k < 30; k++) a = fmaf(r[k], sWe[k * 30 + j], a);
        enc[j] = a;
    }
    float* x1o  = out;
    float* enco = out + (size_t)BB * 7;
    float* oo   = out + (size_t)BB * 37;
    #pragma unroll 1
    for (int j = 0; j < 7; j++) {
        float a = sbr[j];
        #pragma unroll
        for (int k = 0; k < 30; k++) a = fmaf(enc[k], sWr[k * 7 + j], a);
        x1o[(size_t)b * 7 + j] = a;
    }
    float ge[30];
    #pragma unroll
    for (int k = 0; k < 30; k++) {
        enco[(size_t)b * 30 + k] = enc[k];
        ge[k] = gelu_f(enc[k]);
    }
    #pragma unroll 1
    for (int j = 0; j < 60; j++) {
        float a = sbd[j];
        #pragma unroll
        for (int k = 0; k < 30; k++) a = fmaf(ge[k], sWd[k * 60 + j], a);
        oo[(size_t)b * 60 + j] = a;
    }
}

// ---------------- launch ----------------
extern "C" void kernel_launch(void* const* d_in, const int* in_sizes, int n_in,
                              void* d_out, int out_size) {
    const float* x  = (const float*)d_in[0];
    const int*   ei = (const int*)  d_in[1];
    const float* W1 = (const float*)d_in[2];
    const float* b1 = (const float*)d_in[3];
    const float* W2 = (const float*)d_in[4];
    const float* b2 = (const float*)d_in[5];
    const float* We = (const float*)d_in[6];
    const float* be = (const float*)d_in[7];
    const float* Wd = (const float*)d_in[8];
    const float* bd = (const float*)d_in[9];
    const float* Wr = (const float*)d_in[10];
    const float* br = (const float*)d_in[11];
    float* out = (float*)d_out;

    const int TB = 256;
    const int E8 = EE / 8;  // 12M divisible by 8
    k_init_deg<<<(NN + TB - 1) / TB, TB>>>();
    k_deg<<<(E8 + TB - 1) / TB, TB>>>(ei);
    k_prep<<<(NN + TB - 1) / TB, TB>>>(x);
    k_scatter1<<<(E8 + TB - 1) / TB, TB>>>(ei);
    k_mid<<<(NN + TB - 1) / TB, TB>>>(W1, b1, W2);
    k_scatter2<<<(E8 + TB - 1) / TB, TB>>>(ei);
    k_head<<<(BB + 127) / 128, 128>>>(b2, We, be, Wd, bd, Wr, br, out);
}